// round 15
// baseline (speedup 1.0000x reference)
#include <cuda_runtime.h>
#include <cstdint>

// ============================================================================
// Problem constants: B=2, S=2048, E=2048, A=2048, H=16, HD=128
// ============================================================================
#define SEQ   2048
#define EMB   2048
#define NHEAD 16
#define HDIM  128
#define NBATCH 2
// rows of the "token" matrices: B*S = 4096
#define MTOK  4096

// ============================================================================
// Scratch (allocation-free rule: __device__ globals)
// ============================================================================
__device__ __align__(16) float g_q[(size_t)NBATCH * NHEAD * SEQ * HDIM];     // [b,h,s,d]
__device__ __align__(16) float g_k[(size_t)NBATCH * NHEAD * SEQ * HDIM];
__device__ __align__(16) float g_v[(size_t)NBATCH * NHEAD * SEQ * HDIM];
__device__ __align__(16) float g_attn[(size_t)MTOK * EMB];                   // [b,s, h*128+d]
__device__ __align__(16) float g_cos[SEQ * 64];
__device__ __align__(16) float g_sin[SEQ * 64];

// ============================================================================
// SGEMM: 128x128 tile, BK=16, 256 threads, 8x8 microtile, reg-prefetch
// MODE 1: A = x (param), scatter epilogue into g_q/g_k/g_v (N=6144)
// MODE 2: A = g_attn (global), plain epilogue into C (N=2048)
// ============================================================================
#define BM 128
#define BN 128
#define BK 16

template<int MODE>
__global__ void __launch_bounds__(256)
sgemm128(const float* __restrict__ A, const float* __restrict__ Bm,
         float* __restrict__ C, int K, int N)
{
    __shared__ float As[BK][BM];   // A transposed: As[k][m]
    __shared__ float Bs[BK][BN];   // Bs[k][n]

    const int tid = threadIdx.x;
    const int tx = tid & 15;
    const int ty = tid >> 4;
    const int row0 = blockIdx.y * BM;
    const int col0 = blockIdx.x * BN;

    // loader index maps (bijective over 512 float4 items each)
    const int ar0 = tid >> 2;              // A item 0: row
    const int ar1 = (tid >> 2) + 64;       // A item 1: row
    const int acq = tid & 3;               // A: float4 column within BK
    const int br0 = tid >> 5;              // B item 0: k-row
    const int br1 = (tid >> 5) + 8;        // B item 1: k-row
    const int bcq = tid & 31;              // B: float4 column within BN

    const float* Abase = (MODE == 2) ? g_attn : A;
    const float* Ag = Abase + (size_t)row0 * K;
    const float* Bg = Bm + col0;

    float acc[8][8];
#pragma unroll
    for (int i = 0; i < 8; i++)
#pragma unroll
        for (int j = 0; j < 8; j++) acc[i][j] = 0.f;

    float4 pa0, pa1, pb0, pb1;

    auto ldTiles = [&](int kb) {
        pa0 = *(const float4*)(Ag + (size_t)ar0 * K + kb * BK + acq * 4);
        pa1 = *(const float4*)(Ag + (size_t)ar1 * K + kb * BK + acq * 4);
        pb0 = *(const float4*)(Bg + (size_t)(kb * BK + br0) * N + bcq * 4);
        pb1 = *(const float4*)(Bg + (size_t)(kb * BK + br1) * N + bcq * 4);
    };
    auto stTiles = [&]() {
        As[acq * 4 + 0][ar0] = pa0.x; As[acq * 4 + 1][ar0] = pa0.y;
        As[acq * 4 + 2][ar0] = pa0.z; As[acq * 4 + 3][ar0] = pa0.w;
        As[acq * 4 + 0][ar1] = pa1.x; As[acq * 4 + 1][ar1] = pa1.y;
        As[acq * 4 + 2][ar1] = pa1.z; As[acq * 4 + 3][ar1] = pa1.w;
        *(float4*)&Bs[br0][bcq * 4] = pb0;
        *(float4*)&Bs[br1][bcq * 4] = pb1;
    };

    ldTiles(0);
    stTiles();
    __syncthreads();

    const int nk = K / BK;
    for (int kb = 0; kb < nk; kb++) {
        if (kb + 1 < nk) ldTiles(kb + 1);   // prefetch into registers

#pragma unroll
        for (int k = 0; k < BK; k++) {
            float af[8], bf[8];
            *(float4*)&af[0] = *(const float4*)&As[k][ty * 8];
            *(float4*)&af[4] = *(const float4*)&As[k][ty * 8 + 4];
            *(float4*)&bf[0] = *(const float4*)&Bs[k][tx * 8];
            *(float4*)&bf[4] = *(const float4*)&Bs[k][tx * 8 + 4];
#pragma unroll
            for (int i = 0; i < 8; i++)
#pragma unroll
                for (int j = 0; j < 8; j++)
                    acc[i][j] += af[i] * bf[j];
        }
        __syncthreads();
        if (kb + 1 < nk) {
            stTiles();
            __syncthreads();
        }
    }

    if (MODE == 2) {
        // plain epilogue -> C [MTOK, N]
#pragma unroll
        for (int i = 0; i < 8; i++) {
            float* p = C + (size_t)(row0 + ty * 8 + i) * N + col0 + tx * 8;
            *(float4*)p       = make_float4(acc[i][0], acc[i][1], acc[i][2], acc[i][3]);
            *(float4*)(p + 4) = make_float4(acc[i][4], acc[i][5], acc[i][6], acc[i][7]);
        }
    } else {
        // QKV scatter: col tile (128 wide) maps to exactly one (t, head)
        const int t  = col0 >> 11;              // 0=q 1=k 2=v
        const int hh = (col0 & 2047) >> 7;      // head
        float* dst = (t == 0) ? g_q : ((t == 1) ? g_k : g_v);
#pragma unroll
        for (int i = 0; i < 8; i++) {
            const int m = row0 + ty * 8 + i;
            const int b = m >> 11;
            const int s = m & 2047;
            float* p = dst + (((size_t)(b * NHEAD + hh) * SEQ + s) << 7) + tx * 8;
            *(float4*)p       = make_float4(acc[i][0], acc[i][1], acc[i][2], acc[i][3]);
            *(float4*)(p + 4) = make_float4(acc[i][4], acc[i][5], acc[i][6], acc[i][7]);
        }
    }
}

// ============================================================================
// RoPE: table precompute (131072 sincos) + in-place apply on g_q, g_k
// ============================================================================
__global__ void rope_table_kernel()
{
    const int idx = blockIdx.x * 256 + threadIdx.x;   // 0..131071
    const int s = idx >> 6;
    const int j = idx & 63;
    // inv_freq = 10000^(-(2j)/128);  ln(10000) = 9.210340371976184
    const float inv = expf(-((float)(2 * j) * (1.0f / 128.0f)) * 9.210340371976184f);
    const float ang = (float)s * inv;
    g_cos[idx] = cosf(ang);
    g_sin[idx] = sinf(ang);
}

__global__ void rope_apply_kernel()
{
    // 2 * B*H*S = 131072 rows; 4 rows per block (256 threads, 64 per row)
    const int row = blockIdx.x * 4 + (threadIdx.x >> 6);
    const int j = threadIdx.x & 63;
    float* base = (row < NBATCH * NHEAD * SEQ) ? g_q : g_k;
    const int r = row & (NBATCH * NHEAD * SEQ - 1);
    const int s = r & (SEQ - 1);
    float2* p = (float2*)(base + (size_t)r * HDIM) + j;
    const float2 v = *p;
    const float c  = g_cos[(s << 6) + j];
    const float sn = g_sin[(s << 6) + j];
    *p = make_float2(v.x * c - v.y * sn, v.x * sn + v.y * c);
}

// ============================================================================
// Fused flash-style attention.
// Block: 64 query rows of one (b,h); iterate key tiles of 64; online softmax.
// 256 threads as 16x16: GEMM1 microtile 4x4 (S), GEMM2 microtile 4x8 (O).
// ============================================================================
#define KS_LD 129   // padded stride for K tile (odd -> 2-way max bank conflict)
#define PS_LD 65    // padded stride for P^T tile
#define ATT_SMEM_FLOATS (64*128 + 64*KS_LD + 64*128 + 64*PS_LD)
#define ATT_SMEM_BYTES  (ATT_SMEM_FLOATS * 4)

__global__ void __launch_bounds__(256) attn_kernel()
{
    extern __shared__ float sm[];
    float* Qs = sm;                         // [64][128] natural
    float* Ks = Qs + 64 * 128;              // [64][129] natural, padded
    float* Vs = Ks + 64 * KS_LD;            // [64][128] natural
    float* Ps = Vs + 64 * 128;              // [kk][r] transposed, stride 65

    const int tid = threadIdx.x;
    const int tx = tid & 15;
    const int ty = tid >> 4;
    const int bh = blockIdx.y;              // b*16 + h
    const int q0 = blockIdx.x * 64;

    const float* Qg = g_q + (size_t)bh * (SEQ * HDIM);
    const float* Kg = g_k + (size_t)bh * (SEQ * HDIM);
    const float* Vg = g_v + (size_t)bh * (SEQ * HDIM);

    // load Q tile (once)
#pragma unroll
    for (int it = 0; it < 8; it++) {
        const int f = tid + it * 256;
        const int r = f >> 5, c4 = f & 31;
        *(float4*)&Qs[r * 128 + c4 * 4] =
            *(const float4*)(Qg + (size_t)(q0 + r) * HDIM + c4 * 4);
    }

    float m_i[4], l_i[4], O[4][8];
#pragma unroll
    for (int i = 0; i < 4; i++) {
        m_i[i] = -1e30f; l_i[i] = 0.f;
#pragma unroll
        for (int j = 0; j < 8; j++) O[i][j] = 0.f;
    }

    const float scale = 0.08838834764831845f;   // 1/sqrt(128)

    for (int kt = 0; kt < SEQ; kt += 64) {
        __syncthreads();   // Q ready (iter 0) / previous GEMM2 done

        // load K (padded stride) and V tiles
#pragma unroll
        for (int it = 0; it < 8; it++) {
            const int f = tid + it * 256;
            const int r = f >> 5, c4 = f & 31;
            const float4 kv = *(const float4*)(Kg + (size_t)(kt + r) * HDIM + c4 * 4);
            Ks[r * KS_LD + c4 * 4 + 0] = kv.x;
            Ks[r * KS_LD + c4 * 4 + 1] = kv.y;
            Ks[r * KS_LD + c4 * 4 + 2] = kv.z;
            Ks[r * KS_LD + c4 * 4 + 3] = kv.w;
            *(float4*)&Vs[r * 128 + c4 * 4] =
                *(const float4*)(Vg + (size_t)(kt + r) * HDIM + c4 * 4);
        }
        __syncthreads();

        // GEMM1: S[4][4] = Q[ty*4+i][:] . K[tx*4+j][:]
        float sacc[4][4];
#pragma unroll
        for (int i = 0; i < 4; i++)
#pragma unroll
            for (int j = 0; j < 4; j++) sacc[i][j] = 0.f;

#pragma unroll 4
        for (int d = 0; d < HDIM; d++) {
            float qv[4], kv[4];
#pragma unroll
            for (int i = 0; i < 4; i++) qv[i] = Qs[(ty * 4 + i) * 128 + d];
#pragma unroll
            for (int j = 0; j < 4; j++) kv[j] = Ks[(tx * 4 + j) * KS_LD + d];
#pragma unroll
            for (int i = 0; i < 4; i++)
#pragma unroll
                for (int j = 0; j < 4; j++)
                    sacc[i][j] += qv[i] * kv[j];
        }

        // online softmax update (row reductions across the 16 tx lanes)
#pragma unroll
        for (int i = 0; i < 4; i++) {
            float rmax = -1e30f;
#pragma unroll
            for (int j = 0; j < 4; j++) {
                sacc[i][j] *= scale;
                rmax = fmaxf(rmax, sacc[i][j]);
            }
#pragma unroll
            for (int off = 8; off >= 1; off >>= 1)
                rmax = fmaxf(rmax, __shfl_xor_sync(0xffffffffu, rmax, off));

            const float mnew = fmaxf(m_i[i], rmax);
            const float corr = __expf(m_i[i] - mnew);
            float p[4];
            float rsum = 0.f;
#pragma unroll
            for (int j = 0; j < 4; j++) {
                p[j] = __expf(sacc[i][j] - mnew);
                rsum += p[j];
            }
#pragma unroll
            for (int off = 8; off >= 1; off >>= 1)
                rsum += __shfl_xor_sync(0xffffffffu, rsum, off);

            l_i[i] = l_i[i] * corr + rsum;
            m_i[i] = mnew;
#pragma unroll
            for (int j = 0; j < 8; j++) O[i][j] *= corr;
#pragma unroll
            for (int j = 0; j < 4; j++)
                Ps[(tx * 4 + j) * PS_LD + ty * 4 + i] = p[j];
        }
        __syncthreads();

        // GEMM2: O[4][8] += P[r][kk] * V[kk][c]
#pragma unroll 2
        for (int kk = 0; kk < 64; kk++) {
            float pv[4];
#pragma unroll
            for (int i = 0; i < 4; i++) pv[i] = Ps[kk * PS_LD + ty * 4 + i];
            const float4 v0 = *(const float4*)&Vs[kk * 128 + tx * 8];
            const float4 v1 = *(const float4*)&Vs[kk * 128 + tx * 8 + 4];
#pragma unroll
            for (int i = 0; i < 4; i++) {
                O[i][0] += pv[i] * v0.x; O[i][1] += pv[i] * v0.y;
                O[i][2] += pv[i] * v0.z; O[i][3] += pv[i] * v0.w;
                O[i][4] += pv[i] * v1.x; O[i][5] += pv[i] * v1.y;
                O[i][6] += pv[i] * v1.z; O[i][7] += pv[i] * v1.w;
            }
        }
    }

    // epilogue: write in [b, s, h*128+d] layout for the out-projection
    const int hh = bh & 15;
    const int b  = bh >> 4;
#pragma unroll
    for (int i = 0; i < 4; i++) {
        const float inv = 1.f / l_i[i];
        const int sq = q0 + ty * 4 + i;
        float* p = g_attn + ((size_t)(b * SEQ + sq) * EMB) + hh * HDIM + tx * 8;
        *(float4*)p       = make_float4(O[i][0] * inv, O[i][1] * inv,
                                        O[i][2] * inv, O[i][3] * inv);
        *(float4*)(p + 4) = make_float4(O[i][4] * inv, O[i][5] * inv,
                                        O[i][6] * inv, O[i][7] * inv);
    }
}

// ============================================================================
// Launch
// ============================================================================
extern "C" void kernel_launch(void* const* d_in, const int* in_sizes, int n_in,
                              void* d_out, int out_size)
{
    const float* x    = (const float*)d_in[0];   // [B,S,E]
    const float* Wqkv = (const float*)d_in[1];   // [E, 3A]
    const float* Wout = (const float*)d_in[2];   // [A, E]
    float* out = (float*)d_out;                  // [B,S,E]
    (void)in_sizes; (void)n_in; (void)out_size;

    cudaFuncSetAttribute(attn_kernel,
                         cudaFuncAttributeMaxDynamicSharedMemorySize,
                         ATT_SMEM_BYTES);

    // 1) QKV GEMM with scatter epilogue into [b,h,s,d] scratch
    sgemm128<1><<<dim3(6144 / BN, MTOK / BM), 256>>>(x, Wqkv, nullptr, EMB, 3 * EMB);

    // 2) RoPE (table + apply) on Q and K
    rope_table_kernel<<<(SEQ * 64) / 256, 256>>>();
    rope_apply_kernel<<<(2 * NBATCH * NHEAD * SEQ) / 4, 256>>>();

    // 3) fused attention -> g_attn in [b,s,h*d] layout
    attn_kernel<<<dim3(SEQ / 64, NBATCH * NHEAD), 256, ATT_SMEM_BYTES>>>();

    // 4) output projection
    sgemm128<2><<<dim3(EMB / BN, MTOK / BM), 256>>>(nullptr, Wout, out, EMB, EMB);
}

// round 16
// speedup vs baseline: 1.0000x; 1.0000x over previous
#include <cuda_runtime.h>
#include <cstdint>

// ============================================================================
// Problem constants: B=2, S=2048, E=2048, A=2048, H=16, HD=128
// ============================================================================
#define SEQ   2048
#define EMB   2048
#define NHEAD 16
#define HDIM  128
#define NBATCH 2
// rows of the "token" matrices: B*S = 4096
#define MTOK  4096

// ============================================================================
// Scratch (allocation-free rule: __device__ globals)
// ============================================================================
__device__ __align__(16) float g_q[(size_t)NBATCH * NHEAD * SEQ * HDIM];     // [b,h,s,d]
__device__ __align__(16) float g_k[(size_t)NBATCH * NHEAD * SEQ * HDIM];
__device__ __align__(16) float g_v[(size_t)NBATCH * NHEAD * SEQ * HDIM];
__device__ __align__(16) float g_attn[(size_t)MTOK * EMB];                   // [b,s, h*128+d]
__device__ __align__(16) float g_cos[SEQ * 64];
__device__ __align__(16) float g_sin[SEQ * 64];

// ============================================================================
// SGEMM: 128x128 tile, BK=16, 256 threads, 8x8 microtile, reg-prefetch
// MODE 1: A = x (param), scatter epilogue into g_q/g_k/g_v (N=6144)
// MODE 2: A = g_attn (global), plain epilogue into C (N=2048)
// ============================================================================
#define BM 128
#define BN 128
#define BK 16

template<int MODE>
__global__ void __launch_bounds__(256)
sgemm128(const float* __restrict__ A, const float* __restrict__ Bm,
         float* __restrict__ C, int K, int N)
{
    __shared__ float As[BK][BM];   // A transposed: As[k][m]
    __shared__ float Bs[BK][BN];   // Bs[k][n]

    const int tid = threadIdx.x;
    const int tx = tid & 15;
    const int ty = tid >> 4;
    const int row0 = blockIdx.y * BM;
    const int col0 = blockIdx.x * BN;

    // loader index maps (bijective over 512 float4 items each)
    const int ar0 = tid >> 2;              // A item 0: row
    const int ar1 = (tid >> 2) + 64;       // A item 1: row
    const int acq = tid & 3;               // A: float4 column within BK
    const int br0 = tid >> 5;              // B item 0: k-row
    const int br1 = (tid >> 5) + 8;        // B item 1: k-row
    const int bcq = tid & 31;              // B: float4 column within BN

    const float* Abase = (MODE == 2) ? g_attn : A;
    const float* Ag = Abase + (size_t)row0 * K;
    const float* Bg = Bm + col0;

    float acc[8][8];
#pragma unroll
    for (int i = 0; i < 8; i++)
#pragma unroll
        for (int j = 0; j < 8; j++) acc[i][j] = 0.f;

    float4 pa0, pa1, pb0, pb1;

    auto ldTiles = [&](int kb) {
        pa0 = *(const float4*)(Ag + (size_t)ar0 * K + kb * BK + acq * 4);
        pa1 = *(const float4*)(Ag + (size_t)ar1 * K + kb * BK + acq * 4);
        pb0 = *(const float4*)(Bg + (size_t)(kb * BK + br0) * N + bcq * 4);
        pb1 = *(const float4*)(Bg + (size_t)(kb * BK + br1) * N + bcq * 4);
    };
    auto stTiles = [&]() {
        As[acq * 4 + 0][ar0] = pa0.x; As[acq * 4 + 1][ar0] = pa0.y;
        As[acq * 4 + 2][ar0] = pa0.z; As[acq * 4 + 3][ar0] = pa0.w;
        As[acq * 4 + 0][ar1] = pa1.x; As[acq * 4 + 1][ar1] = pa1.y;
        As[acq * 4 + 2][ar1] = pa1.z; As[acq * 4 + 3][ar1] = pa1.w;
        *(float4*)&Bs[br0][bcq * 4] = pb0;
        *(float4*)&Bs[br1][bcq * 4] = pb1;
    };

    ldTiles(0);
    stTiles();
    __syncthreads();

    const int nk = K / BK;
    for (int kb = 0; kb < nk; kb++) {
        if (kb + 1 < nk) ldTiles(kb + 1);   // prefetch into registers

#pragma unroll
        for (int k = 0; k < BK; k++) {
            float af[8], bf[8];
            *(float4*)&af[0] = *(const float4*)&As[k][ty * 8];
            *(float4*)&af[4] = *(const float4*)&As[k][ty * 8 + 4];
            *(float4*)&bf[0] = *(const float4*)&Bs[k][tx * 8];
            *(float4*)&bf[4] = *(const float4*)&Bs[k][tx * 8 + 4];
#pragma unroll
            for (int i = 0; i < 8; i++)
#pragma unroll
                for (int j = 0; j < 8; j++)
                    acc[i][j] += af[i] * bf[j];
        }
        __syncthreads();
        if (kb + 1 < nk) {
            stTiles();
            __syncthreads();
        }
    }

    if (MODE == 2) {
        // plain epilogue -> C [MTOK, N]
#pragma unroll
        for (int i = 0; i < 8; i++) {
            float* p = C + (size_t)(row0 + ty * 8 + i) * N + col0 + tx * 8;
            *(float4*)p       = make_float4(acc[i][0], acc[i][1], acc[i][2], acc[i][3]);
            *(float4*)(p + 4) = make_float4(acc[i][4], acc[i][5], acc[i][6], acc[i][7]);
        }
    } else {
        // QKV scatter: col tile (128 wide) maps to exactly one (t, head)
        const int t  = col0 >> 11;              // 0=q 1=k 2=v
        const int hh = (col0 & 2047) >> 7;      // head
        float* dst = (t == 0) ? g_q : ((t == 1) ? g_k : g_v);
#pragma unroll
        for (int i = 0; i < 8; i++) {
            const int m = row0 + ty * 8 + i;
            const int b = m >> 11;
            const int s = m & 2047;
            float* p = dst + (((size_t)(b * NHEAD + hh) * SEQ + s) << 7) + tx * 8;
            *(float4*)p       = make_float4(acc[i][0], acc[i][1], acc[i][2], acc[i][3]);
            *(float4*)(p + 4) = make_float4(acc[i][4], acc[i][5], acc[i][6], acc[i][7]);
        }
    }
}

// ============================================================================
// RoPE: table precompute (131072 sincos) + in-place apply on g_q, g_k
// ============================================================================
__global__ void rope_table_kernel()
{
    const int idx = blockIdx.x * 256 + threadIdx.x;   // 0..131071
    const int s = idx >> 6;
    const int j = idx & 63;
    // inv_freq = 10000^(-(2j)/128);  ln(10000) = 9.210340371976184
    const float inv = expf(-((float)(2 * j) * (1.0f / 128.0f)) * 9.210340371976184f);
    const float ang = (float)s * inv;
    g_cos[idx] = cosf(ang);
    g_sin[idx] = sinf(ang);
}

__global__ void rope_apply_kernel()
{
    // 2 * B*H*S = 131072 rows; 4 rows per block (256 threads, 64 per row)
    const int row = blockIdx.x * 4 + (threadIdx.x >> 6);
    const int j = threadIdx.x & 63;
    float* base = (row < NBATCH * NHEAD * SEQ) ? g_q : g_k;
    const int r = row & (NBATCH * NHEAD * SEQ - 1);
    const int s = r & (SEQ - 1);
    float2* p = (float2*)(base + (size_t)r * HDIM) + j;
    const float2 v = *p;
    const float c  = g_cos[(s << 6) + j];
    const float sn = g_sin[(s << 6) + j];
    *p = make_float2(v.x * c - v.y * sn, v.x * sn + v.y * c);
}

// ============================================================================
// Fused flash-style attention.
// Block: 64 query rows of one (b,h); iterate key tiles of 64; online softmax.
// 256 threads as 16x16: GEMM1 microtile 4x4 (S), GEMM2 microtile 4x8 (O).
// ============================================================================
#define KS_LD 129   // padded stride for K tile (odd -> 2-way max bank conflict)
#define PS_LD 65    // padded stride for P^T tile
#define ATT_SMEM_FLOATS (64*128 + 64*KS_LD + 64*128 + 64*PS_LD)
#define ATT_SMEM_BYTES  (ATT_SMEM_FLOATS * 4)

__global__ void __launch_bounds__(256) attn_kernel()
{
    extern __shared__ float sm[];
    float* Qs = sm;                         // [64][128] natural
    float* Ks = Qs + 64 * 128;              // [64][129] natural, padded
    float* Vs = Ks + 64 * KS_LD;            // [64][128] natural
    float* Ps = Vs + 64 * 128;              // [kk][r] transposed, stride 65

    const int tid = threadIdx.x;
    const int tx = tid & 15;
    const int ty = tid >> 4;
    const int bh = blockIdx.y;              // b*16 + h
    const int q0 = blockIdx.x * 64;

    const float* Qg = g_q + (size_t)bh * (SEQ * HDIM);
    const float* Kg = g_k + (size_t)bh * (SEQ * HDIM);
    const float* Vg = g_v + (size_t)bh * (SEQ * HDIM);

    // load Q tile (once)
#pragma unroll
    for (int it = 0; it < 8; it++) {
        const int f = tid + it * 256;
        const int r = f >> 5, c4 = f & 31;
        *(float4*)&Qs[r * 128 + c4 * 4] =
            *(const float4*)(Qg + (size_t)(q0 + r) * HDIM + c4 * 4);
    }

    float m_i[4], l_i[4], O[4][8];
#pragma unroll
    for (int i = 0; i < 4; i++) {
        m_i[i] = -1e30f; l_i[i] = 0.f;
#pragma unroll
        for (int j = 0; j < 8; j++) O[i][j] = 0.f;
    }

    const float scale = 0.08838834764831845f;   // 1/sqrt(128)

    for (int kt = 0; kt < SEQ; kt += 64) {
        __syncthreads();   // Q ready (iter 0) / previous GEMM2 done

        // load K (padded stride) and V tiles
#pragma unroll
        for (int it = 0; it < 8; it++) {
            const int f = tid + it * 256;
            const int r = f >> 5, c4 = f & 31;
            const float4 kv = *(const float4*)(Kg + (size_t)(kt + r) * HDIM + c4 * 4);
            Ks[r * KS_LD + c4 * 4 + 0] = kv.x;
            Ks[r * KS_LD + c4 * 4 + 1] = kv.y;
            Ks[r * KS_LD + c4 * 4 + 2] = kv.z;
            Ks[r * KS_LD + c4 * 4 + 3] = kv.w;
            *(float4*)&Vs[r * 128 + c4 * 4] =
                *(const float4*)(Vg + (size_t)(kt + r) * HDIM + c4 * 4);
        }
        __syncthreads();

        // GEMM1: S[4][4] = Q[ty*4+i][:] . K[tx*4+j][:]
        float sacc[4][4];
#pragma unroll
        for (int i = 0; i < 4; i++)
#pragma unroll
            for (int j = 0; j < 4; j++) sacc[i][j] = 0.f;

#pragma unroll 4
        for (int d = 0; d < HDIM; d++) {
            float qv[4], kv[4];
#pragma unroll
            for (int i = 0; i < 4; i++) qv[i] = Qs[(ty * 4 + i) * 128 + d];
#pragma unroll
            for (int j = 0; j < 4; j++) kv[j] = Ks[(tx * 4 + j) * KS_LD + d];
#pragma unroll
            for (int i = 0; i < 4; i++)
#pragma unroll
                for (int j = 0; j < 4; j++)
                    sacc[i][j] += qv[i] * kv[j];
        }

        // online softmax update (row reductions across the 16 tx lanes)
#pragma unroll
        for (int i = 0; i < 4; i++) {
            float rmax = -1e30f;
#pragma unroll
            for (int j = 0; j < 4; j++) {
                sacc[i][j] *= scale;
                rmax = fmaxf(rmax, sacc[i][j]);
            }
#pragma unroll
            for (int off = 8; off >= 1; off >>= 1)
                rmax = fmaxf(rmax, __shfl_xor_sync(0xffffffffu, rmax, off));

            const float mnew = fmaxf(m_i[i], rmax);
            const float corr = __expf(m_i[i] - mnew);
            float p[4];
            float rsum = 0.f;
#pragma unroll
            for (int j = 0; j < 4; j++) {
                p[j] = __expf(sacc[i][j] - mnew);
                rsum += p[j];
            }
#pragma unroll
            for (int off = 8; off >= 1; off >>= 1)
                rsum += __shfl_xor_sync(0xffffffffu, rsum, off);

            l_i[i] = l_i[i] * corr + rsum;
            m_i[i] = mnew;
#pragma unroll
            for (int j = 0; j < 8; j++) O[i][j] *= corr;
#pragma unroll
            for (int j = 0; j < 4; j++)
                Ps[(tx * 4 + j) * PS_LD + ty * 4 + i] = p[j];
        }
        __syncthreads();

        // GEMM2: O[4][8] += P[r][kk] * V[kk][c]
#pragma unroll 2
        for (int kk = 0; kk < 64; kk++) {
            float pv[4];
#pragma unroll
            for (int i = 0; i < 4; i++) pv[i] = Ps[kk * PS_LD + ty * 4 + i];
            const float4 v0 = *(const float4*)&Vs[kk * 128 + tx * 8];
            const float4 v1 = *(const float4*)&Vs[kk * 128 + tx * 8 + 4];
#pragma unroll
            for (int i = 0; i < 4; i++) {
                O[i][0] += pv[i] * v0.x; O[i][1] += pv[i] * v0.y;
                O[i][2] += pv[i] * v0.z; O[i][3] += pv[i] * v0.w;
                O[i][4] += pv[i] * v1.x; O[i][5] += pv[i] * v1.y;
                O[i][6] += pv[i] * v1.z; O[i][7] += pv[i] * v1.w;
            }
        }
    }

    // epilogue: write in [b, s, h*128+d] layout for the out-projection
    const int hh = bh & 15;
    const int b  = bh >> 4;
#pragma unroll
    for (int i = 0; i < 4; i++) {
        const float inv = 1.f / l_i[i];
        const int sq = q0 + ty * 4 + i;
        float* p = g_attn + ((size_t)(b * SEQ + sq) * EMB) + hh * HDIM + tx * 8;
        *(float4*)p       = make_float4(O[i][0] * inv, O[i][1] * inv,
                                        O[i][2] * inv, O[i][3] * inv);
        *(float4*)(p + 4) = make_float4(O[i][4] * inv, O[i][5] * inv,
                                        O[i][6] * inv, O[i][7] * inv);
    }
}

// ============================================================================
// Launch
// ============================================================================
extern "C" void kernel_launch(void* const* d_in, const int* in_sizes, int n_in,
                              void* d_out, int out_size)
{
    const float* x    = (const float*)d_in[0];   // [B,S,E]
    const float* Wqkv = (const float*)d_in[1];   // [E, 3A]
    const float* Wout = (const float*)d_in[2];   // [A, E]
    float* out = (float*)d_out;                  // [B,S,E]
    (void)in_sizes; (void)n_in; (void)out_size;

    cudaFuncSetAttribute(attn_kernel,
                         cudaFuncAttributeMaxDynamicSharedMemorySize,
                         ATT_SMEM_BYTES);

    // 1) QKV GEMM with scatter epilogue into [b,h,s,d] scratch
    sgemm128<1><<<dim3(6144 / BN, MTOK / BM), 256>>>(x, Wqkv, nullptr, EMB, 3 * EMB);

    // 2) RoPE (table + apply) on Q and K
    rope_table_kernel<<<(SEQ * 64) / 256, 256>>>();
    rope_apply_kernel<<<(2 * NBATCH * NHEAD * SEQ) / 4, 256>>>();

    // 3) fused attention -> g_attn in [b,s,h*d] layout
    attn_kernel<<<dim3(SEQ / 64, NBATCH * NHEAD), 256, ATT_SMEM_BYTES>>>();

    // 4) output projection
    sgemm128<2><<<dim3(EMB / BN, MTOK / BM), 256>>>(nullptr, Wout, out, EMB, EMB);
}

// round 17
// speedup vs baseline: 1.0014x; 1.0014x over previous
#include <cuda_runtime.h>
#include <cstdint>

// ============================================================================
// Problem constants: B=2, S=2048, E=2048, A=2048, H=16, HD=128
// ============================================================================
#define SEQ   2048
#define EMB   2048
#define NHEAD 16
#define HDIM  128
#define NBATCH 2
// rows of the "token" matrices: B*S = 4096
#define MTOK  4096

// ============================================================================
// Scratch (allocation-free rule: __device__ globals)
// ============================================================================
__device__ __align__(16) float g_q[(size_t)NBATCH * NHEAD * SEQ * HDIM];     // [b,h,s,d]
__device__ __align__(16) float g_k[(size_t)NBATCH * NHEAD * SEQ * HDIM];
__device__ __align__(16) float g_v[(size_t)NBATCH * NHEAD * SEQ * HDIM];
__device__ __align__(16) float g_attn[(size_t)MTOK * EMB];                   // [b,s, h*128+d]
__device__ __align__(16) float g_cos[SEQ * 64];
__device__ __align__(16) float g_sin[SEQ * 64];

// ============================================================================
// SGEMM: 128x128 tile, BK=16, 256 threads, 8x8 microtile, reg-prefetch
// MODE 1: A = x (param), scatter epilogue into g_q/g_k/g_v (N=6144)
// MODE 2: A = g_attn (global), plain epilogue into C (N=2048)
// ============================================================================
#define BM 128
#define BN 128
#define BK 16

template<int MODE>
__global__ void __launch_bounds__(256)
sgemm128(const float* __restrict__ A, const float* __restrict__ Bm,
         float* __restrict__ C, int K, int N)
{
    __shared__ float As[BK][BM];   // A transposed: As[k][m]
    __shared__ float Bs[BK][BN];   // Bs[k][n]

    const int tid = threadIdx.x;
    const int tx = tid & 15;
    const int ty = tid >> 4;
    const int row0 = blockIdx.y * BM;
    const int col0 = blockIdx.x * BN;

    // loader index maps (bijective over 512 float4 items each)
    const int ar0 = tid >> 2;              // A item 0: row
    const int ar1 = (tid >> 2) + 64;       // A item 1: row
    const int acq = tid & 3;               // A: float4 column within BK
    const int br0 = tid >> 5;              // B item 0: k-row
    const int br1 = (tid >> 5) + 8;        // B item 1: k-row
    const int bcq = tid & 31;              // B: float4 column within BN

    const float* Abase = (MODE == 2) ? g_attn : A;
    const float* Ag = Abase + (size_t)row0 * K;
    const float* Bg = Bm + col0;

    float acc[8][8];
#pragma unroll
    for (int i = 0; i < 8; i++)
#pragma unroll
        for (int j = 0; j < 8; j++) acc[i][j] = 0.f;

    float4 pa0, pa1, pb0, pb1;

    auto ldTiles = [&](int kb) {
        pa0 = *(const float4*)(Ag + (size_t)ar0 * K + kb * BK + acq * 4);
        pa1 = *(const float4*)(Ag + (size_t)ar1 * K + kb * BK + acq * 4);
        pb0 = *(const float4*)(Bg + (size_t)(kb * BK + br0) * N + bcq * 4);
        pb1 = *(const float4*)(Bg + (size_t)(kb * BK + br1) * N + bcq * 4);
    };
    auto stTiles = [&]() {
        As[acq * 4 + 0][ar0] = pa0.x; As[acq * 4 + 1][ar0] = pa0.y;
        As[acq * 4 + 2][ar0] = pa0.z; As[acq * 4 + 3][ar0] = pa0.w;
        As[acq * 4 + 0][ar1] = pa1.x; As[acq * 4 + 1][ar1] = pa1.y;
        As[acq * 4 + 2][ar1] = pa1.z; As[acq * 4 + 3][ar1] = pa1.w;
        *(float4*)&Bs[br0][bcq * 4] = pb0;
        *(float4*)&Bs[br1][bcq * 4] = pb1;
    };

    ldTiles(0);
    stTiles();
    __syncthreads();

    const int nk = K / BK;
    for (int kb = 0; kb < nk; kb++) {
        if (kb + 1 < nk) ldTiles(kb + 1);   // prefetch into registers

#pragma unroll
        for (int k = 0; k < BK; k++) {
            float af[8], bf[8];
            *(float4*)&af[0] = *(const float4*)&As[k][ty * 8];
            *(float4*)&af[4] = *(const float4*)&As[k][ty * 8 + 4];
            *(float4*)&bf[0] = *(const float4*)&Bs[k][tx * 8];
            *(float4*)&bf[4] = *(const float4*)&Bs[k][tx * 8 + 4];
#pragma unroll
            for (int i = 0; i < 8; i++)
#pragma unroll
                for (int j = 0; j < 8; j++)
                    acc[i][j] += af[i] * bf[j];
        }
        __syncthreads();
        if (kb + 1 < nk) {
            stTiles();
            __syncthreads();
        }
    }

    if (MODE == 2) {
        // plain epilogue -> C [MTOK, N]
#pragma unroll
        for (int i = 0; i < 8; i++) {
            float* p = C + (size_t)(row0 + ty * 8 + i) * N + col0 + tx * 8;
            *(float4*)p       = make_float4(acc[i][0], acc[i][1], acc[i][2], acc[i][3]);
            *(float4*)(p + 4) = make_float4(acc[i][4], acc[i][5], acc[i][6], acc[i][7]);
        }
    } else {
        // QKV scatter: col tile (128 wide) maps to exactly one (t, head)
        const int t  = col0 >> 11;              // 0=q 1=k 2=v
        const int hh = (col0 & 2047) >> 7;      // head
        float* dst = (t == 0) ? g_q : ((t == 1) ? g_k : g_v);
#pragma unroll
        for (int i = 0; i < 8; i++) {
            const int m = row0 + ty * 8 + i;
            const int b = m >> 11;
            const int s = m & 2047;
            float* p = dst + (((size_t)(b * NHEAD + hh) * SEQ + s) << 7) + tx * 8;
            *(float4*)p       = make_float4(acc[i][0], acc[i][1], acc[i][2], acc[i][3]);
            *(float4*)(p + 4) = make_float4(acc[i][4], acc[i][5], acc[i][6], acc[i][7]);
        }
    }
}

// ============================================================================
// RoPE: table precompute (131072 sincos) + in-place apply on g_q, g_k
// ============================================================================
__global__ void rope_table_kernel()
{
    const int idx = blockIdx.x * 256 + threadIdx.x;   // 0..131071
    const int s = idx >> 6;
    const int j = idx & 63;
    // inv_freq = 10000^(-(2j)/128);  ln(10000) = 9.210340371976184
    const float inv = expf(-((float)(2 * j) * (1.0f / 128.0f)) * 9.210340371976184f);
    const float ang = (float)s * inv;
    g_cos[idx] = cosf(ang);
    g_sin[idx] = sinf(ang);
}

__global__ void rope_apply_kernel()
{
    // 2 * B*H*S = 131072 rows; 4 rows per block (256 threads, 64 per row)
    const int row = blockIdx.x * 4 + (threadIdx.x >> 6);
    const int j = threadIdx.x & 63;
    float* base = (row < NBATCH * NHEAD * SEQ) ? g_q : g_k;
    const int r = row & (NBATCH * NHEAD * SEQ - 1);
    const int s = r & (SEQ - 1);
    float2* p = (float2*)(base + (size_t)r * HDIM) + j;
    const float2 v = *p;
    const float c  = g_cos[(s << 6) + j];
    const float sn = g_sin[(s << 6) + j];
    *p = make_float2(v.x * c - v.y * sn, v.x * sn + v.y * c);
}

// ============================================================================
// Fused flash-style attention.
// Block: 64 query rows of one (b,h); iterate key tiles of 64; online softmax.
// 256 threads as 16x16: GEMM1 microtile 4x4 (S), GEMM2 microtile 4x8 (O).
// ============================================================================
#define KS_LD 129   // padded stride for K tile (odd -> 2-way max bank conflict)
#define PS_LD 65    // padded stride for P^T tile
#define ATT_SMEM_FLOATS (64*128 + 64*KS_LD + 64*128 + 64*PS_LD)
#define ATT_SMEM_BYTES  (ATT_SMEM_FLOATS * 4)

__global__ void __launch_bounds__(256) attn_kernel()
{
    extern __shared__ float sm[];
    float* Qs = sm;                         // [64][128] natural
    float* Ks = Qs + 64 * 128;              // [64][129] natural, padded
    float* Vs = Ks + 64 * KS_LD;            // [64][128] natural
    float* Ps = Vs + 64 * 128;              // [kk][r] transposed, stride 65

    const int tid = threadIdx.x;
    const int tx = tid & 15;
    const int ty = tid >> 4;
    const int bh = blockIdx.y;              // b*16 + h
    const int q0 = blockIdx.x * 64;

    const float* Qg = g_q + (size_t)bh * (SEQ * HDIM);
    const float* Kg = g_k + (size_t)bh * (SEQ * HDIM);
    const float* Vg = g_v + (size_t)bh * (SEQ * HDIM);

    // load Q tile (once)
#pragma unroll
    for (int it = 0; it < 8; it++) {
        const int f = tid + it * 256;
        const int r = f >> 5, c4 = f & 31;
        *(float4*)&Qs[r * 128 + c4 * 4] =
            *(const float4*)(Qg + (size_t)(q0 + r) * HDIM + c4 * 4);
    }

    float m_i[4], l_i[4], O[4][8];
#pragma unroll
    for (int i = 0; i < 4; i++) {
        m_i[i] = -1e30f; l_i[i] = 0.f;
#pragma unroll
        for (int j = 0; j < 8; j++) O[i][j] = 0.f;
    }

    const float scale = 0.08838834764831845f;   // 1/sqrt(128)

    for (int kt = 0; kt < SEQ; kt += 64) {
        __syncthreads();   // Q ready (iter 0) / previous GEMM2 done

        // load K (padded stride) and V tiles
#pragma unroll
        for (int it = 0; it < 8; it++) {
            const int f = tid + it * 256;
            const int r = f >> 5, c4 = f & 31;
            const float4 kv = *(const float4*)(Kg + (size_t)(kt + r) * HDIM + c4 * 4);
            Ks[r * KS_LD + c4 * 4 + 0] = kv.x;
            Ks[r * KS_LD + c4 * 4 + 1] = kv.y;
            Ks[r * KS_LD + c4 * 4 + 2] = kv.z;
            Ks[r * KS_LD + c4 * 4 + 3] = kv.w;
            *(float4*)&Vs[r * 128 + c4 * 4] =
                *(const float4*)(Vg + (size_t)(kt + r) * HDIM + c4 * 4);
        }
        __syncthreads();

        // GEMM1: S[4][4] = Q[ty*4+i][:] . K[tx*4+j][:]
        float sacc[4][4];
#pragma unroll
        for (int i = 0; i < 4; i++)
#pragma unroll
            for (int j = 0; j < 4; j++) sacc[i][j] = 0.f;

#pragma unroll 4
        for (int d = 0; d < HDIM; d++) {
            float qv[4], kv[4];
#pragma unroll
            for (int i = 0; i < 4; i++) qv[i] = Qs[(ty * 4 + i) * 128 + d];
#pragma unroll
            for (int j = 0; j < 4; j++) kv[j] = Ks[(tx * 4 + j) * KS_LD + d];
#pragma unroll
            for (int i = 0; i < 4; i++)
#pragma unroll
                for (int j = 0; j < 4; j++)
                    sacc[i][j] += qv[i] * kv[j];
        }

        // online softmax update (row reductions across the 16 tx lanes)
#pragma unroll
        for (int i = 0; i < 4; i++) {
            float rmax = -1e30f;
#pragma unroll
            for (int j = 0; j < 4; j++) {
                sacc[i][j] *= scale;
                rmax = fmaxf(rmax, sacc[i][j]);
            }
#pragma unroll
            for (int off = 8; off >= 1; off >>= 1)
                rmax = fmaxf(rmax, __shfl_xor_sync(0xffffffffu, rmax, off));

            const float mnew = fmaxf(m_i[i], rmax);
            const float corr = __expf(m_i[i] - mnew);
            float p[4];
            float rsum = 0.f;
#pragma unroll
            for (int j = 0; j < 4; j++) {
                p[j] = __expf(sacc[i][j] - mnew);
                rsum += p[j];
            }
#pragma unroll
            for (int off = 8; off >= 1; off >>= 1)
                rsum += __shfl_xor_sync(0xffffffffu, rsum, off);

            l_i[i] = l_i[i] * corr + rsum;
            m_i[i] = mnew;
#pragma unroll
            for (int j = 0; j < 8; j++) O[i][j] *= corr;
#pragma unroll
            for (int j = 0; j < 4; j++)
                Ps[(tx * 4 + j) * PS_LD + ty * 4 + i] = p[j];
        }
        __syncthreads();

        // GEMM2: O[4][8] += P[r][kk] * V[kk][c]
#pragma unroll 2
        for (int kk = 0; kk < 64; kk++) {
            float pv[4];
#pragma unroll
            for (int i = 0; i < 4; i++) pv[i] = Ps[kk * PS_LD + ty * 4 + i];
            const float4 v0 = *(const float4*)&Vs[kk * 128 + tx * 8];
            const float4 v1 = *(const float4*)&Vs[kk * 128 + tx * 8 + 4];
#pragma unroll
            for (int i = 0; i < 4; i++) {
                O[i][0] += pv[i] * v0.x; O[i][1] += pv[i] * v0.y;
                O[i][2] += pv[i] * v0.z; O[i][3] += pv[i] * v0.w;
                O[i][4] += pv[i] * v1.x; O[i][5] += pv[i] * v1.y;
                O[i][6] += pv[i] * v1.z; O[i][7] += pv[i] * v1.w;
            }
        }
    }

    // epilogue: write in [b, s, h*128+d] layout for the out-projection
    const int hh = bh & 15;
    const int b  = bh >> 4;
#pragma unroll
    for (int i = 0; i < 4; i++) {
        const float inv = 1.f / l_i[i];
        const int sq = q0 + ty * 4 + i;
        float* p = g_attn + ((size_t)(b * SEQ + sq) * EMB) + hh * HDIM + tx * 8;
        *(float4*)p       = make_float4(O[i][0] * inv, O[i][1] * inv,
                                        O[i][2] * inv, O[i][3] * inv);
        *(float4*)(p + 4) = make_float4(O[i][4] * inv, O[i][5] * inv,
                                        O[i][6] * inv, O[i][7] * inv);
    }
}

// ============================================================================
// Launch
// ============================================================================
extern "C" void kernel_launch(void* const* d_in, const int* in_sizes, int n_in,
                              void* d_out, int out_size)
{
    const float* x    = (const float*)d_in[0];   // [B,S,E]
    const float* Wqkv = (const float*)d_in[1];   // [E, 3A]
    const float* Wout = (const float*)d_in[2];   // [A, E]
    float* out = (float*)d_out;                  // [B,S,E]
    (void)in_sizes; (void)n_in; (void)out_size;

    cudaFuncSetAttribute(attn_kernel,
                         cudaFuncAttributeMaxDynamicSharedMemorySize,
                         ATT_SMEM_BYTES);

    // 1) QKV GEMM with scatter epilogue into [b,h,s,d] scratch
    sgemm128<1><<<dim3(6144 / BN, MTOK / BM), 256>>>(x, Wqkv, nullptr, EMB, 3 * EMB);

    // 2) RoPE (table + apply) on Q and K
    rope_table_kernel<<<(SEQ * 64) / 256, 256>>>();
    rope_apply_kernel<<<(2 * NBATCH * NHEAD * SEQ) / 4, 256>>>();

    // 3) fused attention -> g_attn in [b,s,h*d] layout
    attn_kernel<<<dim3(SEQ / 64, NBATCH * NHEAD), 256, ATT_SMEM_BYTES>>>();

    // 4) output projection
    sgemm128<2><<<dim3(EMB / BN, MTOK / BM), 256>>>(nullptr, Wout, out, EMB, EMB);
}